// round 13
// baseline (speedup 1.0000x reference)
#include <cuda_runtime.h>
#include <cstdint>
#include <math.h>

namespace {
constexpr int T_ = 2048;          // tokens = S*B
constexpr int H_ = 1024;
constexpr int F_ = 4096;
constexpr int E_ = 4;

// GEMM tiling: block 128(M) x 256(N) x 32(K), 8 warps as 2(M) x 4(N), warp 64x64
constexpr int BM = 128, BN = 256, BK = 32;
constexpr int STAGES = 4;
constexpr int ASTR = 36;                          // A smem row stride (floats)
constexpr int BSTR = 264;                         // B smem row stride (floats)
constexpr int A_BYTES = BM * ASTR * 4;            // 18432
constexpr int B_BYTES = BK * BSTR * 4;            // 33792
constexpr int STAGE_BYTES = A_BYTES + B_BYTES;    // 52224 (multiple of 16)
constexpr int HDR = 1024;                         // smem header: sidx[128] + ticket
constexpr int SMEM_BYTES = HDR + STAGES * STAGE_BYTES;   // 209920
constexpr int NB1 = F_ / BN;                      // 16 fc1 n-blocks
constexpr int NB2 = H_ / BN;                      // 4  fc2 n-blocks
constexpr int GRID_P = 148;                       // persistent CTAs (1/SM)
}

// Scratch (__device__ globals per allocation rules)
__device__ float g_act[(size_t)E_ * T_ * F_];     // compacted fc1 out (tf32-rounded)
__device__ float g_y  [(size_t)E_ * T_ * H_];     // compacted fc2 out
__device__ int   g_idx[E_ * T_];                  // per-expert gathered token ids
__device__ int   g_rowmap[T_ * E_];               // token -> compact row (or -1)
__device__ int   g_cnt[E_];
__device__ int   g_t1, g_t2;                      // tile tickets
__device__ int   g_done[E_ * 16];                 // fc1 n-tiles done per (e, m-block)

__device__ __forceinline__ float to_tf32(float x) {
    unsigned r; asm("cvt.rna.tf32.f32 %0, %1;" : "=r"(r) : "f"(x));
    return __uint_as_float(r);
}
__device__ __forceinline__ unsigned tf32u(float x) {
    unsigned r; asm("cvt.rna.tf32.f32 %0, %1;" : "=r"(r) : "f"(x));
    return r;
}
__device__ __forceinline__ float gelu_exact(float x) {
    return 0.5f * x * (1.0f + erff(x * 0.70710678118654752f));
}
__device__ __forceinline__ uint32_t s2u(const void* p) {
    uint32_t a;
    asm("{ .reg .u64 t; cvta.to.shared.u64 t, %1; cvt.u32.u64 %0, t; }" : "=r"(a) : "l"(p));
    return a;
}
__device__ __forceinline__ void cpa16(uint32_t d, const void* s) {
    asm volatile("cp.async.cg.shared.global [%0], [%1], 16;" :: "r"(d), "l"(s));
}
__device__ __forceinline__ void mma8(float* c, const unsigned* a, const unsigned* b) {
    asm volatile(
        "mma.sync.aligned.m16n8k8.row.col.f32.tf32.tf32.f32 "
        "{%0,%1,%2,%3}, {%4,%5,%6,%7}, {%8,%9}, {%0,%1,%2,%3};"
        : "+f"(c[0]), "+f"(c[1]), "+f"(c[2]), "+f"(c[3])
        : "r"(a[0]), "r"(a[1]), "r"(a[2]), "r"(a[3]), "r"(b[0]), "r"(b[1]));
}

// ---------------------------------------------------------------------------
// Core multistage GEMM: C[128,256] += A[128, kTiles*32] @ B[kTiles*32, 256]
// Raw fp32 operands; tf32(rna) rounding applied at fragment load.
// A rows optionally gathered through sidx (smem header).
// ---------------------------------------------------------------------------
template <bool GATHER>
__device__ __forceinline__ void gemm_main(
    const float* __restrict__ Abase, int lda,
    const float* __restrict__ Bg, int ldb,
    int kTiles, const int* __restrict__ sidx,
    float c[4][8][4])
{
    extern __shared__ char smem[];
    const uint32_t sb = s2u(smem);
    const int tid = threadIdx.x;

    auto fill = [&](int kt, int stage) {
        uint32_t as = sb + HDR + stage * STAGE_BYTES;
        uint32_t bs = as + A_BYTES;
#pragma unroll
        for (int i = 0; i < 4; i++) {                 // A: 128 rows x 128B
            int idx = i * 256 + tid;
            int row = idx >> 3, seg = idx & 7;
            const float* src = GATHER
                ? Abase + (size_t)sidx[row] * lda + kt * BK + seg * 4
                : Abase + (size_t)row * lda + kt * BK + seg * 4;
            cpa16(as + (uint32_t)(row * ASTR + seg * 4) * 4, src);
        }
#pragma unroll
        for (int i = 0; i < 8; i++) {                 // B: 32 rows x 1024B
            int idx = i * 256 + tid;
            int k = idx >> 6, seg = idx & 63;
            cpa16(bs + (uint32_t)(k * BSTR + seg * 4) * 4,
                  Bg + (size_t)(kt * BK + k) * ldb + seg * 4);
        }
        asm volatile("cp.async.commit_group;" ::: "memory");
    };

#pragma unroll
    for (int s = 0; s < STAGES - 1; s++) fill(s, s);

    const int lane = tid & 31;
    const int q = lane >> 2, r = lane & 3;
    const int wm = ((tid >> 5) >> 2) * 64;            // 2 warps in M
    const int wn = ((tid >> 5) & 3) * 64;             // 4 warps in N

    for (int kt = 0; kt < kTiles; kt++) {
        asm volatile("cp.async.wait_group %0;" :: "n"(STAGES - 2) : "memory");
        __syncthreads();
        int f = kt + STAGES - 1;
        if (f < kTiles) fill(f, f % STAGES);
        else asm volatile("cp.async.commit_group;" ::: "memory");

        const float* Ac = (const float*)(smem + HDR + (kt % STAGES) * STAGE_BYTES);
        const float* Bc = (const float*)((const char*)Ac + A_BYTES);
#pragma unroll
        for (int ks = 0; ks < 4; ks++) {
            unsigned af[4][4], bf[8][2];
            const int acol = ks * 8 + r;
#pragma unroll
            for (int mi = 0; mi < 4; mi++) {
                int row = wm + q + mi * 16;
                af[mi][0] = tf32u(Ac[row * ASTR + acol]);
                af[mi][1] = tf32u(Ac[(row + 8) * ASTR + acol]);
                af[mi][2] = tf32u(Ac[row * ASTR + acol + 4]);
                af[mi][3] = tf32u(Ac[(row + 8) * ASTR + acol + 4]);
            }
            const int brow = ks * 8 + r;
#pragma unroll
            for (int ni = 0; ni < 8; ni++) {
                int cc = wn + ni * 8 + q;
                bf[ni][0] = tf32u(Bc[brow * BSTR + cc]);
                bf[ni][1] = tf32u(Bc[(brow + 4) * BSTR + cc]);
            }
#pragma unroll
            for (int mi = 0; mi < 4; mi++)
#pragma unroll
                for (int ni = 0; ni < 8; ni++)
                    mma8(c[mi][ni], af[mi], bf[ni]);
        }
    }
}

// ---------------------------------------------------------------------------
// Fused persistent MoE kernel: fc1 tile queue, then fc2 tile queue with
// per-(e, m-block) dependency counters.
// ---------------------------------------------------------------------------
__global__ void __launch_bounds__(256, 1) moe_kernel(
    const float* __restrict__ x, const float* __restrict__ probs,
    const float* __restrict__ w1, const float* __restrict__ w2)
{
    extern __shared__ char smem[];
    int* shdr = (int*)smem;                 // [0..127] sidx, [128] ticket
    const int tid = threadIdx.x;
    const int lane = tid & 31;
    const int q = lane >> 2, r = lane & 3;
    const int wm = ((tid >> 5) >> 2) * 64;
    const int wn = ((tid >> 5) & 3) * 64;

    int cnt[E_], mb[E_];
#pragma unroll
    for (int e = 0; e < E_; e++) { cnt[e] = g_cnt[e]; mb[e] = (cnt[e] + BM - 1) / BM; }
    const int mbsum = mb[0] + mb[1] + mb[2] + mb[3];
    const int n1 = NB1 * mbsum;
    const int n2 = NB2 * mbsum;

    // ---------------- Phase 1: fc1 tiles, (e, m)-major ----------------
    for (;;) {
        if (tid == 0) shdr[128] = atomicAdd(&g_t1, 1);
        __syncthreads();
        const int t = shdr[128];
        __syncthreads();
        if (t >= n1) break;
        int e = 0, off = t;
        while (e < E_ - 1 && off >= mb[e] * NB1) { off -= mb[e] * NB1; e++; }
        const int mbk = off / NB1, nb = off % NB1;
        const int m_base = mbk * BM, n_base = nb * BN;

        if (tid < BM) shdr[tid] = g_idx[e * T_ + m_base + tid];
        __syncthreads();

        float c[4][8][4];
#pragma unroll
        for (int i = 0; i < 4; i++)
#pragma unroll
            for (int j = 0; j < 8; j++)
#pragma unroll
                for (int k = 0; k < 4; k++) c[i][j][k] = 0.f;

        gemm_main<true>(x, H_, w1 + (size_t)e * H_ * F_ + n_base, F_,
                        H_ / BK, shdr, c);

        const int ce = cnt[e];
#pragma unroll
        for (int mi = 0; mi < 4; mi++) {
            int row0 = wm + q + mi * 16, row1 = row0 + 8;
            int s0 = m_base + row0, s1 = m_base + row1;
            bool v0 = s0 < ce, v1 = s1 < ce;
            float p0 = v0 ? probs[(size_t)shdr[row0] * E_ + e] : 0.f;
            float p1 = v1 ? probs[(size_t)shdr[row1] * E_ + e] : 0.f;
#pragma unroll
            for (int ni = 0; ni < 8; ni++) {
                int col = n_base + wn + ni * 8 + r * 2;
                if (v0) {
                    float2 o;
                    o.x = to_tf32(gelu_exact(c[mi][ni][0]) * p0);
                    o.y = to_tf32(gelu_exact(c[mi][ni][1]) * p0);
                    *reinterpret_cast<float2*>(&g_act[((size_t)(e * T_ + s0)) * F_ + col]) = o;
                }
                if (v1) {
                    float2 o;
                    o.x = to_tf32(gelu_exact(c[mi][ni][2]) * p1);
                    o.y = to_tf32(gelu_exact(c[mi][ni][3]) * p1);
                    *reinterpret_cast<float2*>(&g_act[((size_t)(e * T_ + s1)) * F_ + col]) = o;
                }
            }
        }
        __threadfence();            // every thread flushes its g_act stores
        __syncthreads();
        if (tid == 0) atomicAdd(&g_done[e * 16 + mbk], 1);
    }

    // ---------------- Phase 2: fc2 tiles ----------------
    for (;;) {
        if (tid == 0) shdr[128] = atomicAdd(&g_t2, 1);
        __syncthreads();
        const int t = shdr[128];
        __syncthreads();
        if (t >= n2) break;
        int e = 0, off = t;
        while (e < E_ - 1 && off >= mb[e] * NB2) { off -= mb[e] * NB2; e++; }
        const int mbk = off / NB2, nb = off % NB2;
        const int m_base = mbk * BM, n_base = nb * BN;

        if (tid == 0) {             // wait for all 16 fc1 n-tiles of (e, mbk)
            while (atomicAdd(&g_done[e * 16 + mbk], 0) < NB1) __nanosleep(100);
        }
        __syncthreads();
        __threadfence();            // acquire side; A fills use cp.async.cg (L2 reads)

        float c[4][8][4];
#pragma unroll
        for (int i = 0; i < 4; i++)
#pragma unroll
            for (int j = 0; j < 8; j++)
#pragma unroll
                for (int k = 0; k < 4; k++) c[i][j][k] = 0.f;

        gemm_main<false>(g_act + (size_t)(e * T_ + m_base) * F_, F_,
                         w2 + (size_t)e * F_ * H_ + n_base, H_,
                         F_ / BK, nullptr, c);

        const int ce = cnt[e];
#pragma unroll
        for (int mi = 0; mi < 4; mi++) {
            int row0 = wm + q + mi * 16, row1 = row0 + 8;
            int s0 = m_base + row0, s1 = m_base + row1;
#pragma unroll
            for (int ni = 0; ni < 8; ni++) {
                int col = n_base + wn + ni * 8 + r * 2;
                if (s0 < ce) {
                    float2 o = make_float2(c[mi][ni][0], c[mi][ni][1]);
                    *reinterpret_cast<float2*>(&g_y[((size_t)(e * T_ + s0)) * H_ + col]) = o;
                }
                if (s1 < ce) {
                    float2 o = make_float2(c[mi][ni][2], c[mi][ni][3]);
                    *reinterpret_cast<float2*>(&g_y[((size_t)(e * T_ + s1)) * H_ + col]) = o;
                }
            }
        }
    }
}

// Deterministic per-expert ordered compaction (1 block / expert) + state reset
__global__ void __launch_bounds__(512) compact_kernel(const float* __restrict__ probs)
{
    const int e = blockIdx.x;
    const int tid = threadIdx.x;               // 512 threads, 4 tokens each
    if (e == 0) {                              // reset fused-kernel state
        if (tid == 0) { g_t1 = 0; g_t2 = 0; }
        if (tid < E_ * 16) g_done[tid] = 0;
    }
    __shared__ int ssum[512];
    __shared__ int scnt;
    const int t0 = tid * 4;
    int f[4], loc = 0;
#pragma unroll
    for (int j = 0; j < 4; j++) {
        f[j] = (probs[(size_t)(t0 + j) * E_ + e] != 0.f) ? 1 : 0;
        loc += f[j];
    }
    ssum[tid] = loc;
    __syncthreads();
    for (int off = 1; off < 512; off <<= 1) {   // inclusive Hillis-Steele scan
        int v = ssum[tid];
        int u = (tid >= off) ? ssum[tid - off] : 0;
        __syncthreads();
        ssum[tid] = v + u;
        __syncthreads();
    }
    int pos = ssum[tid] - loc;                 // exclusive base, token-ordered
    if (tid == 511) scnt = ssum[511];
    __syncthreads();
    const int cnt = scnt;
#pragma unroll
    for (int j = 0; j < 4; j++) {
        int t = t0 + j;
        if (f[j]) {
            g_idx[e * T_ + pos] = t;
            g_rowmap[t * E_ + e] = e * T_ + pos;
            pos++;
        } else {
            g_rowmap[t * E_ + e] = -1;
        }
    }
    if (tid == 0) g_cnt[e] = cnt;
    for (int i = tid; i < T_; i += 512)
        if (i >= cnt) g_idx[e * T_ + i] = 0;   // safe gather target for padded rows
}

// out[t] = resid[t] + sum over routed experts of y[row]
__global__ void __launch_bounds__(256) combine_kernel(
    const float* __restrict__ resid, float* __restrict__ out)
{
    const int i = blockIdx.x * 256 + threadIdx.x;    // float4 index over T*H/4
    const int t = i >> 8;                            // H/4 = 256
    const int co = (i & 255) * 4;
    int4 rm = *reinterpret_cast<const int4*>(&g_rowmap[t * E_]);
    float4 v = reinterpret_cast<const float4*>(resid)[i];
    if (rm.x >= 0) { float4 a = *reinterpret_cast<const float4*>(&g_y[(size_t)rm.x * H_ + co]);
                     v.x += a.x; v.y += a.y; v.z += a.z; v.w += a.w; }
    if (rm.y >= 0) { float4 a = *reinterpret_cast<const float4*>(&g_y[(size_t)rm.y * H_ + co]);
                     v.x += a.x; v.y += a.y; v.z += a.z; v.w += a.w; }
    if (rm.z >= 0) { float4 a = *reinterpret_cast<const float4*>(&g_y[(size_t)rm.z * H_ + co]);
                     v.x += a.x; v.y += a.y; v.z += a.z; v.w += a.w; }
    if (rm.w >= 0) { float4 a = *reinterpret_cast<const float4*>(&g_y[(size_t)rm.w * H_ + co]);
                     v.x += a.x; v.y += a.y; v.z += a.z; v.w += a.w; }
    reinterpret_cast<float4*>(out)[i] = v;
}

extern "C" void kernel_launch(void* const* d_in, const int* in_sizes, int n_in,
                              void* d_out, int out_size) {
    (void)in_sizes; (void)n_in; (void)out_size;
    const float* x     = (const float*)d_in[0];   // [T, H]
    const float* resid = (const float*)d_in[1];   // [T, H]
    const float* probs = (const float*)d_in[2];   // [T, E] masked+renormalized
    // d_in[3] routing_map: redundant (probs is exactly 0 off the top-k)
    const float* w1    = (const float*)d_in[4];   // [E, H, F]
    const float* w2    = (const float*)d_in[5];   // [E, F, H]
    float* out = (float*)d_out;

    cudaFuncSetAttribute(moe_kernel, cudaFuncAttributeMaxDynamicSharedMemorySize, SMEM_BYTES);

    compact_kernel<<<E_, 512>>>(probs);
    moe_kernel<<<GRID_P, 256, SMEM_BYTES>>>(x, probs, w1, w2);
    combine_kernel<<<T_ * H_ / 4 / 256, 256>>>(resid, out);
}

// round 15
// speedup vs baseline: 1.0140x; 1.0140x over previous
#include <cuda_runtime.h>
#include <cstdint>
#include <math.h>

namespace {
constexpr int T_ = 2048;          // tokens = S*B
constexpr int H_ = 1024;
constexpr int F_ = 4096;
constexpr int E_ = 4;

// GEMM tiling: block 128(M) x 256(N) x 32(K), 8 warps as 2(M) x 4(N), warp 64x64
constexpr int BM = 128, BN = 256, BK = 32;
constexpr int STAGES = 4;
constexpr int ASTR = 36;                          // A smem row stride (floats)
constexpr int BSTR = 264;                         // B smem row stride (floats)
constexpr int A_BYTES = BM * ASTR * 4;            // 18432
constexpr int B_BYTES = BK * BSTR * 4;            // 33792
constexpr int STAGE_BYTES = A_BYTES + B_BYTES;    // 52224 (multiple of 16)
constexpr int HDR = 1024;                         // smem header: sidx[128] + ticket
constexpr int SMEM_BYTES = HDR + STAGES * STAGE_BYTES;   // 209920
constexpr int NB1 = F_ / BN;                      // 16 fc1 n-blocks
constexpr int NB2 = H_ / BN;                      // 4  fc2 n-blocks
constexpr int GRID_P = 148;                       // persistent CTAs (1/SM)
}

// Scratch (__device__ globals per allocation rules)
__device__ float g_x  [(size_t)T_ * H_];          // tf32-rounded X
__device__ float g_w1r[(size_t)E_ * H_ * F_];     // tf32-rounded W1
__device__ float g_w2r[(size_t)E_ * F_ * H_];     // tf32-rounded W2
__device__ float g_act[(size_t)E_ * T_ * F_];     // compacted fc1 out (tf32-rounded)
__device__ float g_y  [(size_t)E_ * T_ * H_];     // compacted fc2 out
__device__ int   g_idx[E_ * T_];                  // per-expert gathered token ids
__device__ int   g_rowmap[T_ * E_];               // token -> compact row (or -1)
__device__ int   g_cnt[E_];
__device__ int   g_t1, g_t2;                      // tile tickets
__device__ int   g_done[E_ * 16];                 // fc1 n-tiles done per (e, m-block)

__device__ __forceinline__ float to_tf32(float x) {
    unsigned r; asm("cvt.rna.tf32.f32 %0, %1;" : "=r"(r) : "f"(x));
    return __uint_as_float(r);
}
__device__ __forceinline__ float gelu_exact(float x) {
    return 0.5f * x * (1.0f + erff(x * 0.70710678118654752f));
}
__device__ __forceinline__ uint32_t s2u(const void* p) {
    uint32_t a;
    asm("{ .reg .u64 t; cvta.to.shared.u64 t, %1; cvt.u32.u64 %0, t; }" : "=r"(a) : "l"(p));
    return a;
}
__device__ __forceinline__ void cpa16(uint32_t d, const void* s) {
    asm volatile("cp.async.cg.shared.global [%0], [%1], 16;" :: "r"(d), "l"(s));
}
__device__ __forceinline__ void mma8(float* c, const unsigned* a, const unsigned* b) {
    asm volatile(
        "mma.sync.aligned.m16n8k8.row.col.f32.tf32.tf32.f32 "
        "{%0,%1,%2,%3}, {%4,%5,%6,%7}, {%8,%9}, {%0,%1,%2,%3};"
        : "+f"(c[0]), "+f"(c[1]), "+f"(c[2]), "+f"(c[3])
        : "r"(a[0]), "r"(a[1]), "r"(a[2]), "r"(a[3]), "r"(b[0]), "r"(b[1]));
}

// Fragment loaders (operands pre-rounded to tf32; plain bit loads)
__device__ __forceinline__ void load_afrag(
    const float* __restrict__ Ac, int ks, int wm, int q, int r, unsigned af[4][4])
{
    const int acol = ks * 8 + r;
#pragma unroll
    for (int mi = 0; mi < 4; mi++) {
        int row = wm + q + mi * 16;
        af[mi][0] = __float_as_uint(Ac[row * ASTR + acol]);
        af[mi][1] = __float_as_uint(Ac[(row + 8) * ASTR + acol]);
        af[mi][2] = __float_as_uint(Ac[row * ASTR + acol + 4]);
        af[mi][3] = __float_as_uint(Ac[(row + 8) * ASTR + acol + 4]);
    }
}
__device__ __forceinline__ void load_bfrag(
    const float* __restrict__ Bc, int ks, int wn, int q, int r, unsigned bf[8][2])
{
    const int brow = ks * 8 + r;
#pragma unroll
    for (int ni = 0; ni < 8; ni++) {
        int cc = wn + ni * 8 + q;
        bf[ni][0] = __float_as_uint(Bc[brow * BSTR + cc]);
        bf[ni][1] = __float_as_uint(Bc[(brow + 4) * BSTR + cc]);
    }
}

// ---------------------------------------------------------------------------
// Core multistage GEMM: C[128,256] += A[128, kTiles*32] @ B[kTiles*32, 256]
// Fragment double-buffering: load ks+1 while issuing MMAs for ks.
// A rows optionally gathered through sidx (smem header).
// ---------------------------------------------------------------------------
template <bool GATHER>
__device__ __forceinline__ void gemm_main(
    const float* __restrict__ Abase, int lda,
    const float* __restrict__ Bg, int ldb,
    int kTiles, const int* __restrict__ sidx,
    float c[4][8][4])
{
    extern __shared__ char smem[];
    const uint32_t sb = s2u(smem);
    const int tid = threadIdx.x;

    auto fill = [&](int kt, int stage) {
        uint32_t as = sb + HDR + stage * STAGE_BYTES;
        uint32_t bs = as + A_BYTES;
#pragma unroll
        for (int i = 0; i < 4; i++) {                 // A: 128 rows x 128B
            int idx = i * 256 + tid;
            int row = idx >> 3, seg = idx & 7;
            const float* src = GATHER
                ? Abase + (size_t)sidx[row] * lda + kt * BK + seg * 4
                : Abase + (size_t)row * lda + kt * BK + seg * 4;
            cpa16(as + (uint32_t)(row * ASTR + seg * 4) * 4, src);
        }
#pragma unroll
        for (int i = 0; i < 8; i++) {                 // B: 32 rows x 1024B
            int idx = i * 256 + tid;
            int k = idx >> 6, seg = idx & 63;
            cpa16(bs + (uint32_t)(k * BSTR + seg * 4) * 4,
                  Bg + (size_t)(kt * BK + k) * ldb + seg * 4);
        }
        asm volatile("cp.async.commit_group;" ::: "memory");
    };

#pragma unroll
    for (int s = 0; s < STAGES - 1; s++) fill(s, s);

    const int lane = tid & 31;
    const int q = lane >> 2, r = lane & 3;
    const int wm = ((tid >> 5) >> 2) * 64;            // 2 warps in M
    const int wn = ((tid >> 5) & 3) * 64;             // 4 warps in N

    unsigned af[2][4][4], bf[2][8][2];

    for (int kt = 0; kt < kTiles; kt++) {
        asm volatile("cp.async.wait_group %0;" :: "n"(STAGES - 2) : "memory");
        __syncthreads();

        const float* Ac = (const float*)(smem + HDR + (kt % STAGES) * STAGE_BYTES);
        const float* Bc = (const float*)((const char*)Ac + A_BYTES);

        // head fragments first so MMAs start before the fill shadow
        load_afrag(Ac, 0, wm, q, r, af[0]);
        load_bfrag(Bc, 0, wn, q, r, bf[0]);

        int f = kt + STAGES - 1;
        if (f < kTiles) fill(f, f % STAGES);
        else asm volatile("cp.async.commit_group;" ::: "memory");

#pragma unroll
        for (int ks = 0; ks < 4; ks++) {
            const int cur = ks & 1, nxt = cur ^ 1;
            if (ks < 3) {                             // prefetch next k-slice
                load_afrag(Ac, ks + 1, wm, q, r, af[nxt]);
                load_bfrag(Bc, ks + 1, wn, q, r, bf[nxt]);
            }
#pragma unroll
            for (int mi = 0; mi < 4; mi++)
#pragma unroll
                for (int ni = 0; ni < 8; ni++)
                    mma8(c[mi][ni], af[cur][mi], bf[cur][ni]);
        }
    }
}

// ---------------------------------------------------------------------------
// Fused persistent MoE kernel: fc1 tile queue, then fc2 tile queue with
// per-(e, m-block) dependency counters.
// ---------------------------------------------------------------------------
__global__ void __launch_bounds__(256, 1) moe_kernel(const float* __restrict__ probs)
{
    extern __shared__ char smem[];
    int* shdr = (int*)smem;                 // [0..127] sidx, [128] ticket
    const int tid = threadIdx.x;
    const int lane = tid & 31;
    const int q = lane >> 2, r = lane & 3;
    const int wm = ((tid >> 5) >> 2) * 64;
    const int wn = ((tid >> 5) & 3) * 64;

    int cnt[E_], mb[E_];
#pragma unroll
    for (int e = 0; e < E_; e++) { cnt[e] = g_cnt[e]; mb[e] = (cnt[e] + BM - 1) / BM; }
    const int mbsum = mb[0] + mb[1] + mb[2] + mb[3];
    const int n1 = NB1 * mbsum;
    const int n2 = NB2 * mbsum;

    // ---------------- Phase 1: fc1 tiles, (e, m)-major ----------------
    for (;;) {
        if (tid == 0) shdr[128] = atomicAdd(&g_t1, 1);
        __syncthreads();
        const int t = shdr[128];
        __syncthreads();
        if (t >= n1) break;
        int e = 0, off = t;
        while (e < E_ - 1 && off >= mb[e] * NB1) { off -= mb[e] * NB1; e++; }
        const int mbk = off / NB1, nb = off % NB1;
        const int m_base = mbk * BM, n_base = nb * BN;

        if (tid < BM) shdr[tid] = g_idx[e * T_ + m_base + tid];
        __syncthreads();

        float c[4][8][4];
#pragma unroll
        for (int i = 0; i < 4; i++)
#pragma unroll
            for (int j = 0; j < 8; j++)
#pragma unroll
                for (int k = 0; k < 4; k++) c[i][j][k] = 0.f;

        gemm_main<true>(g_x, H_, g_w1r + (size_t)e * H_ * F_ + n_base, F_,
                        H_ / BK, shdr, c);

        const int ce = cnt[e];
#pragma unroll
        for (int mi = 0; mi < 4; mi++) {
            int row0 = wm + q + mi * 16, row1 = row0 + 8;
            int s0 = m_base + row0, s1 = m_base + row1;
            bool v0 = s0 < ce, v1 = s1 < ce;
            float p0 = v0 ? probs[(size_t)shdr[row0] * E_ + e] : 0.f;
            float p1 = v1 ? probs[(size_t)shdr[row1] * E_ + e] : 0.f;
#pragma unroll
            for (int ni = 0; ni < 8; ni++) {
                int col = n_base + wn + ni * 8 + r * 2;
                if (v0) {
                    float2 o;
                    o.x = to_tf32(gelu_exact(c[mi][ni][0]) * p0);
                    o.y = to_tf32(gelu_exact(c[mi][ni][1]) * p0);
                    *reinterpret_cast<float2*>(&g_act[((size_t)(e * T_ + s0)) * F_ + col]) = o;
                }
                if (v1) {
                    float2 o;
                    o.x = to_tf32(gelu_exact(c[mi][ni][2]) * p1);
                    o.y = to_tf32(gelu_exact(c[mi][ni][3]) * p1);
                    *reinterpret_cast<float2*>(&g_act[((size_t)(e * T_ + s1)) * F_ + col]) = o;
                }
            }
        }
        __threadfence();            // every thread flushes its g_act stores
        __syncthreads();
        if (tid == 0) atomicAdd(&g_done[e * 16 + mbk], 1);
    }

    // ---------------- Phase 2: fc2 tiles ----------------
    for (;;) {
        if (tid == 0) shdr[128] = atomicAdd(&g_t2, 1);
        __syncthreads();
        const int t = shdr[128];
        __syncthreads();
        if (t >= n2) break;
        int e = 0, off = t;
        while (e < E_ - 1 && off >= mb[e] * NB2) { off -= mb[e] * NB2; e++; }
        const int mbk = off / NB2, nb = off % NB2;
        const int m_base = mbk * BM, n_base = nb * BN;

        if (tid == 0) {             // wait for all 16 fc1 n-tiles of (e, mbk)
            while (atomicAdd(&g_done[e * 16 + mbk], 0) < NB1) __nanosleep(100);
        }
        __syncthreads();
        __threadfence();            // acquire side; A fills use cp.async.cg (L2 reads)

        float c[4][8][4];
#pragma unroll
        for (int i = 0; i < 4; i++)
#pragma unroll
            for (int j = 0; j < 8; j++)
#pragma unroll
                for (int k = 0; k < 4; k++) c[i][j][k] = 0.f;

        gemm_main<false>(g_act + (size_t)(e * T_ + m_base) * F_, F_,
                         g_w2r + (size_t)e * F_ * H_ + n_base, H_,
                         F_ / BK, nullptr, c);

        const int ce = cnt[e];
#pragma unroll
        for (int mi = 0; mi < 4; mi++) {
            int row0 = wm + q + mi * 16, row1 = row0 + 8;
            int s0 = m_base + row0, s1 = m_base + row1;
#pragma unroll
            for (int ni = 0; ni < 8; ni++) {
                int col = n_base + wn + ni * 8 + r * 2;
                if (s0 < ce) {
                    float2 o = make_float2(c[mi][ni][0], c[mi][ni][1]);
                    *reinterpret_cast<float2*>(&g_y[((size_t)(e * T_ + s0)) * H_ + col]) = o;
                }
                if (s1 < ce) {
                    float2 o = make_float2(c[mi][ni][2], c[mi][ni][3]);
                    *reinterpret_cast<float2*>(&g_y[((size_t)(e * T_ + s1)) * H_ + col]) = o;
                }
            }
        }
    }
}

// Deterministic per-expert ordered compaction (1 block / expert) + state reset
__global__ void __launch_bounds__(512) compact_kernel(const float* __restrict__ probs)
{
    const int e = blockIdx.x;
    const int tid = threadIdx.x;               // 512 threads, 4 tokens each
    if (e == 0) {                              // reset fused-kernel state
        if (tid == 0) { g_t1 = 0; g_t2 = 0; }
        if (tid < E_ * 16) g_done[tid] = 0;
    }
    __shared__ int ssum[512];
    __shared__ int scnt;
    const int t0 = tid * 4;
    int f[4], loc = 0;
#pragma unroll
    for (int j = 0; j < 4; j++) {
        f[j] = (probs[(size_t)(t0 + j) * E_ + e] != 0.f) ? 1 : 0;
        loc += f[j];
    }
    ssum[tid] = loc;
    __syncthreads();
    for (int off = 1; off < 512; off <<= 1) {   // inclusive Hillis-Steele scan
        int v = ssum[tid];
        int u = (tid >= off) ? ssum[tid - off] : 0;
        __syncthreads();
        ssum[tid] = v + u;
        __syncthreads();
    }
    int pos = ssum[tid] - loc;                 // exclusive base, token-ordered
    if (tid == 511) scnt = ssum[511];
    __syncthreads();
    const int cnt = scnt;
#pragma unroll
    for (int j = 0; j < 4; j++) {
        int t = t0 + j;
        if (f[j]) {
            g_idx[e * T_ + pos] = t;
            g_rowmap[t * E_ + e] = e * T_ + pos;
            pos++;
        } else {
            g_rowmap[t * E_ + e] = -1;
        }
    }
    if (tid == 0) g_cnt[e] = cnt;
    for (int i = tid; i < T_; i += 512)
        if (i >= cnt) g_idx[e * T_ + i] = 0;   // safe gather target for padded rows
}

// out[t] = resid[t] + sum over routed experts of y[row]
__global__ void __launch_bounds__(256) combine_kernel(
    const float* __restrict__ resid, float* __restrict__ out)
{
    const int i = blockIdx.x * 256 + threadIdx.x;    // float4 index over T*H/4
    const int t = i >> 8;                            // H/4 = 256
    const int co = (i & 255) * 4;
    int4 rm = *reinterpret_cast<const int4*>(&g_rowmap[t * E_]);
    float4 v = reinterpret_cast<const float4*>(resid)[i];
    if (rm.x >= 0) { float4 a = *reinterpret_cast<const float4*>(&g_y[(size_t)rm.x * H_ + co]);
                     v.x += a.x; v.y += a.y; v.z += a.z; v.w += a.w; }
    if (rm.y >= 0) { float4 a = *reinterpret_cast<const float4*>(&g_y[(size_t)rm.y * H_ + co]);
                     v.x += a.x; v.y += a.y; v.z += a.z; v.w += a.w; }
    if (rm.z >= 0) { float4 a = *reinterpret_cast<const float4*>(&g_y[(size_t)rm.z * H_ + co]);
                     v.x += a.x; v.y += a.y; v.z += a.z; v.w += a.w; }
    if (rm.w >= 0) { float4 a = *reinterpret_cast<const float4*>(&g_y[(size_t)rm.w * H_ + co]);
                     v.x += a.x; v.y += a.y; v.z += a.z; v.w += a.w; }
    reinterpret_cast<float4*>(out)[i] = v;
}

// tf32-round copy (float4 granularity)
__global__ void __launch_bounds__(256) round_copy_kernel(
    const float* __restrict__ in, float* __restrict__ dst)
{
    size_t i = (size_t)blockIdx.x * 256 + threadIdx.x;
    float4 v = reinterpret_cast<const float4*>(in)[i];
    v.x = to_tf32(v.x); v.y = to_tf32(v.y); v.z = to_tf32(v.z); v.w = to_tf32(v.w);
    reinterpret_cast<float4*>(dst)[i] = v;
}

extern "C" void kernel_launch(void* const* d_in, const int* in_sizes, int n_in,
                              void* d_out, int out_size) {
    (void)in_sizes; (void)n_in; (void)out_size;
    const float* x     = (const float*)d_in[0];   // [T, H]
    const float* resid = (const float*)d_in[1];   // [T, H]
    const float* probs = (const float*)d_in[2];   // [T, E] masked+renormalized
    // d_in[3] routing_map: redundant (probs is exactly 0 off the top-k)
    const float* w1    = (const float*)d_in[4];   // [E, H, F]
    const float* w2    = (const float*)d_in[5];   // [E, F, H]
    float* out = (float*)d_out;

    cudaFuncSetAttribute(moe_kernel, cudaFuncAttributeMaxDynamicSharedMemorySize, SMEM_BYTES);

    float* gx;  cudaGetSymbolAddress((void**)&gx,  g_x);
    float* gw1; cudaGetSymbolAddress((void**)&gw1, g_w1r);
    float* gw2; cudaGetSymbolAddress((void**)&gw2, g_w2r);

    round_copy_kernel<<<T_ * H_ / 4 / 256, 256>>>(x, gx);                    // 8 MB
    round_copy_kernel<<<E_ * H_ * F_ / 4 / 256, 256>>>(w1, gw1);             // 64 MB
    round_copy_kernel<<<E_ * F_ * H_ / 4 / 256, 256>>>(w2, gw2);             // 64 MB
    compact_kernel<<<E_, 512>>>(probs);

    moe_kernel<<<GRID_P, 256, SMEM_BYTES>>>(probs);
    combine_kernel<<<T_ * H_ / 4 / 256, 256>>>(resid, out);
}